// round 6
// baseline (speedup 1.0000x reference)
#include <cuda_runtime.h>
#include <cstdint>

#define B_   8
#define N_   784
#define DIM_ 384
#define H_   12
#define HD_  32
#define GS_  28
#define ROWS_ (B_*N_)   // 6272
#define NB_  (B_*HD_)   // 256
#define SCALE_ 0.28867513459481287f   // 12^-0.5

// Scratch (allocation-free rule: __device__ globals).
// All buffers below (except g_posout) hold tf32 bit patterns.
__device__ float g_xt[ROWS_*DIM_];       // x, tf32 bits
__device__ float g_wqkv[3*DIM_*DIM_];    // [Wq|Wk|Wv], tf32 bits
__device__ float g_wo[DIM_*DIM_];        // W_out, tf32 bits
__device__ float g_q[B_*H_*N_*HD_];
__device__ float g_k[B_*H_*N_*HD_];
__device__ float g_v[B_*H_*N_*HD_];
__device__ float g_vt[H_*N_*NB_];        // [h][m][b*32+d], tf32 bits
__device__ float g_att[B_*N_*DIM_];      // attn output, tf32 bits
__device__ float g_posout[B_*N_*DIM_];   // gate * (pos @ V), fp32
__device__ float g_pos[H_*N_*N_];        // normalized positional scores (tf32 bits)

// ---------------------------------------------------------------------------
// helpers
// ---------------------------------------------------------------------------
__device__ __forceinline__ unsigned f2tf(float f) {
    unsigned r; asm("cvt.rna.tf32.f32 %0, %1;" : "=r"(r) : "f"(f)); return r;
}
__device__ __forceinline__ void mma8(float4& d,
                                     unsigned a0, unsigned a1, unsigned a2, unsigned a3,
                                     unsigned b0, unsigned b1) {
    asm volatile("mma.sync.aligned.m16n8k8.row.col.f32.tf32.tf32.f32 "
                 "{%0,%1,%2,%3}, {%4,%5,%6,%7}, {%8,%9}, {%0,%1,%2,%3};\n"
                 : "+f"(d.x), "+f"(d.y), "+f"(d.z), "+f"(d.w)
                 : "r"(a0), "r"(a1), "r"(a2), "r"(a3), "r"(b0), "r"(b1));
}
__device__ __forceinline__ void cpa16(void* s, const void* g, bool pred) {
    unsigned sa = (unsigned)__cvta_generic_to_shared(s);
    int sz = pred ? 16 : 0;
    asm volatile("cp.async.cg.shared.global [%0], [%1], 16, %2;\n"
                 :: "r"(sa), "l"(g), "r"(sz) : "memory");
}
__device__ __forceinline__ void cpa_commit() {
    asm volatile("cp.async.commit_group;\n" ::: "memory");
}

// ---------------------------------------------------------------------------
// Kernel 0: convert x / Wq|Wk|Wv / W_out to tf32 bit patterns
// ---------------------------------------------------------------------------
__global__ void cvt_kernel(const float* __restrict__ x,
                           const float* __restrict__ Wq,
                           const float* __restrict__ Wk,
                           const float* __restrict__ Wv,
                           const float* __restrict__ Wo) {
    int stride = gridDim.x * blockDim.x;
    const int WSZ = DIM_ * DIM_;
    for (int i = blockIdx.x * blockDim.x + threadIdx.x; i < ROWS_ * DIM_; i += stride)
        g_xt[i] = __uint_as_float(f2tf(x[i]));
    for (int i = blockIdx.x * blockDim.x + threadIdx.x; i < WSZ; i += stride) {
        g_wqkv[i]           = __uint_as_float(f2tf(Wq[i]));
        g_wqkv[WSZ + i]     = __uint_as_float(f2tf(Wk[i]));
        g_wqkv[2 * WSZ + i] = __uint_as_float(f2tf(Wv[i]));
        g_wo[i]             = __uint_as_float(f2tf(Wo[i]));
    }
}

// ---------------------------------------------------------------------------
// Kernel 1: normalized positional softmax  pos[h][n][m]  (writes tf32 bits)
// ---------------------------------------------------------------------------
__global__ void pos_kernel(const float* __restrict__ W_pos,
                           const float* __restrict__ b_pos) {
    int hn = blockIdx.x;
    int h = hn / N_, n = hn - h * N_;
    int nx = n % GS_, ny = n / GS_;
    float w0 = W_pos[h*3+0], w1 = W_pos[h*3+1], w2 = W_pos[h*3+2], bp = b_pos[h];
    int t = threadIdx.x;

    float lg[4];
    float lmax = -1e30f;
#pragma unroll
    for (int i = 0; i < 4; i++) {
        int m = t + i * 256;
        if (m < N_) {
            int mx = m % GS_, my = m / GS_;
            float dx = (float)(mx - nx), dy = (float)(my - ny);
            float v = fmaf(w2, dx*dx + dy*dy, fmaf(w1, dy, fmaf(w0, dx, bp)));
            lg[i] = v;
            lmax = fmaxf(lmax, v);
        } else lg[i] = -1e30f;
    }
    __shared__ float sred[8];
    __shared__ float ssum[8];
#pragma unroll
    for (int o = 16; o > 0; o >>= 1)
        lmax = fmaxf(lmax, __shfl_xor_sync(0xffffffffu, lmax, o));
    if ((t & 31) == 0) sred[t >> 5] = lmax;
    __syncthreads();
    float bmax = fmaxf(fmaxf(fmaxf(sred[0], sred[1]), fmaxf(sred[2], sred[3])),
                       fmaxf(fmaxf(sred[4], sred[5]), fmaxf(sred[6], sred[7])));

    float e[4]; float lsum = 0.f;
#pragma unroll
    for (int i = 0; i < 4; i++) { e[i] = __expf(lg[i] - bmax); lsum += e[i]; }
#pragma unroll
    for (int o = 16; o > 0; o >>= 1)
        lsum += __shfl_xor_sync(0xffffffffu, lsum, o);
    if ((t & 31) == 0) ssum[t >> 5] = lsum;
    __syncthreads();
    float tot = ((ssum[0]+ssum[1])+(ssum[2]+ssum[3]))+((ssum[4]+ssum[5])+(ssum[6]+ssum[7]));
    float inv = 1.f / tot;

    float* outp = g_pos + (size_t)hn * N_;
#pragma unroll
    for (int i = 0; i < 4; i++) {
        int m = t + i * 256;
        if (m < N_) outp[m] = __uint_as_float(f2tf(e[i] * inv));
    }
}

// ---------------------------------------------------------------------------
// Kernel 2: fused QKV tf32 GEMM, cp.async double-buffered.
// Inputs pre-converted (g_xt, g_wqkv). Writes tf32 bits (Q pre-scaled).
// V additionally stored to g_vt[h][m][b*32+d].
// ---------------------------------------------------------------------------
#define GSTR 36
__global__ __launch_bounds__(128) void gemm_qkv() {
    __shared__ unsigned Xs[2][64][GSTR];
    __shared__ unsigned Ws[2][64][GSTR];

    int t = threadIdx.x, w = t >> 5, lane = t & 31;
    int ly = lane >> 2, lx = lane & 3;
    int wr = w >> 1, wc = w & 1;
    int row0 = blockIdx.y * 64, col0 = blockIdx.x * 64;
    int wsel = col0 / DIM_;
    int colw = col0 - wsel * DIM_;
    const unsigned* X = (const unsigned*)g_xt;
    const unsigned* W = (const unsigned*)g_wqkv + (size_t)wsel * DIM_ * DIM_;
    float* Op = (wsel == 0) ? g_q : (wsel == 1) ? g_k : g_v;
    float scale = (wsel == 0) ? SCALE_ : 1.f;

    // stage 0 fill
#pragma unroll
    for (int l = 0; l < 4; l++) {
        int idx = t + l * 128;
        int r = idx >> 3, kq = (idx & 7) << 2;
        cpa16(&Xs[0][r][kq], &X[(size_t)(row0 + r) * DIM_ + kq], true);
        cpa16(&Ws[0][r][kq], &W[(size_t)(colw + r) * DIM_ + kq], true);
    }
    cpa_commit();

    float4 acc[2][4];
#pragma unroll
    for (int i = 0; i < 2; i++)
#pragma unroll
        for (int j = 0; j < 4; j++) acc[i][j] = make_float4(0.f, 0.f, 0.f, 0.f);

    for (int ki = 0; ki < 12; ki++) {
        int cur = ki & 1;
        if (ki < 11) {
            int nxt = (ki + 1) & 1;
            int k0 = (ki + 1) * 32;
#pragma unroll
            for (int l = 0; l < 4; l++) {
                int idx = t + l * 128;
                int r = idx >> 3, kq = (idx & 7) << 2;
                cpa16(&Xs[nxt][r][kq], &X[(size_t)(row0 + r) * DIM_ + k0 + kq], true);
                cpa16(&Ws[nxt][r][kq], &W[(size_t)(colw + r) * DIM_ + k0 + kq], true);
            }
            cpa_commit();
            asm volatile("cp.async.wait_group 1;\n" ::: "memory");
        } else {
            asm volatile("cp.async.wait_group 0;\n" ::: "memory");
        }
        __syncthreads();
#pragma unroll
        for (int kk = 0; kk < 4; kk++) {
            int K0 = kk * 8;
            unsigned a[2][4];
#pragma unroll
            for (int mi = 0; mi < 2; mi++) {
                int rb = wr * 32 + mi * 16 + ly;
                a[mi][0] = Xs[cur][rb][K0 + lx];
                a[mi][1] = Xs[cur][rb + 8][K0 + lx];
                a[mi][2] = Xs[cur][rb][K0 + lx + 4];
                a[mi][3] = Xs[cur][rb + 8][K0 + lx + 4];
            }
#pragma unroll
            for (int nt = 0; nt < 4; nt++) {
                int cb = wc * 32 + nt * 8 + ly;
                unsigned b0 = Ws[cur][cb][K0 + lx];
                unsigned b1 = Ws[cur][cb][K0 + lx + 4];
                mma8(acc[0][nt], a[0][0], a[0][1], a[0][2], a[0][3], b0, b1);
                mma8(acc[1][nt], a[1][0], a[1][1], a[1][2], a[1][3], b0, b1);
            }
        }
        __syncthreads();
    }

    // epilogue: write tf32 bits, [b][h][n][d] layout, Q pre-scaled
    int h = (colw + wc * 32) >> 5;
#pragma unroll
    for (int mi = 0; mi < 2; mi++) {
        int row = row0 + wr * 32 + mi * 16 + ly;
#pragma unroll
        for (int nt = 0; nt < 4; nt++) {
            int d = nt * 8 + lx * 2;
            {
                int b = row / N_, n = row - b * N_;
                float2 v;
                v.x = __uint_as_float(f2tf(acc[mi][nt].x * scale));
                v.y = __uint_as_float(f2tf(acc[mi][nt].y * scale));
                *(float2*)&Op[(((size_t)(b * H_ + h)) * N_ + n) * HD_ + d] = v;
                if (wsel == 2)
                    *(float2*)&g_vt[((size_t)h * N_ + n) * NB_ + b * HD_ + d] = v;
            }
            {
                int row2 = row + 8;
                int b = row2 / N_, n = row2 - b * N_;
                float2 v;
                v.x = __uint_as_float(f2tf(acc[mi][nt].z * scale));
                v.y = __uint_as_float(f2tf(acc[mi][nt].w * scale));
                *(float2*)&Op[(((size_t)(b * H_ + h)) * N_ + n) * HD_ + d] = v;
                if (wsel == 2)
                    *(float2*)&g_vt[((size_t)h * N_ + n) * NB_ + b * HD_ + d] = v;
            }
        }
    }
}

// ---------------------------------------------------------------------------
// Kernel 2b: out-projection tf32 GEMM, cp.async double-buffered.
// X = g_att (tf32 bits), W = g_wo (tf32 bits). + bias, fp32 out.
// ---------------------------------------------------------------------------
__global__ __launch_bounds__(128) void gemm_out(
    const float* __restrict__ bias, float* __restrict__ OUTp)
{
    __shared__ unsigned Xs[2][64][GSTR];
    __shared__ unsigned Ws[2][64][GSTR];

    int t = threadIdx.x, w = t >> 5, lane = t & 31;
    int ly = lane >> 2, lx = lane & 3;
    int wr = w >> 1, wc = w & 1;
    int row0 = blockIdx.y * 64, col0 = blockIdx.x * 64;
    const unsigned* X = (const unsigned*)g_att;
    const unsigned* W = (const unsigned*)g_wo;

#pragma unroll
    for (int l = 0; l < 4; l++) {
        int idx = t + l * 128;
        int r = idx >> 3, kq = (idx & 7) << 2;
        cpa16(&Xs[0][r][kq], &X[(size_t)(row0 + r) * DIM_ + kq], true);
        cpa16(&Ws[0][r][kq], &W[(size_t)(col0 + r) * DIM_ + kq], true);
    }
    cpa_commit();

    float4 acc[2][4];
#pragma unroll
    for (int i = 0; i < 2; i++)
#pragma unroll
        for (int j = 0; j < 4; j++) acc[i][j] = make_float4(0.f, 0.f, 0.f, 0.f);

    for (int ki = 0; ki < 12; ki++) {
        int cur = ki & 1;
        if (ki < 11) {
            int nxt = (ki + 1) & 1;
            int k0 = (ki + 1) * 32;
#pragma unroll
            for (int l = 0; l < 4; l++) {
                int idx = t + l * 128;
                int r = idx >> 3, kq = (idx & 7) << 2;
                cpa16(&Xs[nxt][r][kq], &X[(size_t)(row0 + r) * DIM_ + k0 + kq], true);
                cpa16(&Ws[nxt][r][kq], &W[(size_t)(col0 + r) * DIM_ + k0 + kq], true);
            }
            cpa_commit();
            asm volatile("cp.async.wait_group 1;\n" ::: "memory");
        } else {
            asm volatile("cp.async.wait_group 0;\n" ::: "memory");
        }
        __syncthreads();
#pragma unroll
        for (int kk = 0; kk < 4; kk++) {
            int K0 = kk * 8;
            unsigned a[2][4];
#pragma unroll
            for (int mi = 0; mi < 2; mi++) {
                int rb = wr * 32 + mi * 16 + ly;
                a[mi][0] = Xs[cur][rb][K0 + lx];
                a[mi][1] = Xs[cur][rb + 8][K0 + lx];
                a[mi][2] = Xs[cur][rb][K0 + lx + 4];
                a[mi][3] = Xs[cur][rb + 8][K0 + lx + 4];
            }
#pragma unroll
            for (int nt = 0; nt < 4; nt++) {
                int cb = wc * 32 + nt * 8 + ly;
                unsigned b0 = Ws[cur][cb][K0 + lx];
                unsigned b1 = Ws[cur][cb][K0 + lx + 4];
                mma8(acc[0][nt], a[0][0], a[0][1], a[0][2], a[0][3], b0, b1);
                mma8(acc[1][nt], a[1][0], a[1][1], a[1][2], a[1][3], b0, b1);
            }
        }
        __syncthreads();
    }

#pragma unroll
    for (int mi = 0; mi < 2; mi++) {
        int row = row0 + wr * 32 + mi * 16 + ly;
#pragma unroll
        for (int nt = 0; nt < 4; nt++) {
            int col = col0 + wc * 32 + nt * 8 + lx * 2;
            float b0 = bias[col], b1 = bias[col + 1];
            float2 v0; v0.x = acc[mi][nt].x + b0; v0.y = acc[mi][nt].y + b1;
            *(float2*)&OUTp[(size_t)row * DIM_ + col] = v0;
            float2 v1; v1.x = acc[mi][nt].z + b0; v1.y = acc[mi][nt].w + b1;
            *(float2*)&OUTp[(size_t)(row + 8) * DIM_ + col] = v1;
        }
    }
}

// ---------------------------------------------------------------------------
// Kernel 2c: pos_pv — per head GEMM  g_posout = gate * (pos[h] @ Vt[h])
// Block = 64 n-rows x 256 cols (ALL batches), 256 threads (8 warps, 1x8).
// K = 784 in 25 chunks of 32, cp.async double-buffered.
// pos table read exactly once chip-wide.
// ---------------------------------------------------------------------------
#define BSTR 264   // 256 + 8: sigma=8 -> conflict-free B-frag loads
struct PPSmem {
    unsigned As[2][64][GSTR];   // pos rows x 32k
    unsigned Bs[2][32][BSTR];   // 32k x 256 cols
};

__global__ __launch_bounds__(256) void pos_pv(const float* __restrict__ gating) {
    extern __shared__ char sraw[];
    PPSmem& S = *reinterpret_cast<PPSmem*>(sraw);

    int t = threadIdx.x, w = t >> 5, lane = t & 31;
    int ly = lane >> 2, lx = lane & 3;
    int h = blockIdx.y;
    int n0 = blockIdx.x * 64;

    const unsigned* Pg = (const unsigned*)g_pos + (size_t)h * N_ * N_;
    const unsigned* Vt = (const unsigned*)g_vt + (size_t)h * N_ * NB_;
    float gate = 1.f / (1.f + __expf(-gating[h]));

    // stage 0 fill (k0 = 0)
#pragma unroll
    for (int l = 0; l < 2; l++) {
        int idx = t + l * 256;
        int r = idx >> 3, kq = (idx & 7) << 2;
        cpa16(&S.As[0][r][kq], &Pg[(size_t)(n0 + r) * N_ + kq], n0 + r < N_);
    }
#pragma unroll
    for (int l = 0; l < 8; l++) {
        int idx = t + l * 256;
        int r = idx >> 6, cq = (idx & 63) << 2;
        cpa16(&S.Bs[0][r][cq], &Vt[(size_t)r * NB_ + cq], true);
    }
    cpa_commit();

    float4 acc[4][4];
#pragma unroll
    for (int i = 0; i < 4; i++)
#pragma unroll
        for (int j = 0; j < 4; j++) acc[i][j] = make_float4(0.f, 0.f, 0.f, 0.f);

    for (int ch = 0; ch < 25; ch++) {
        int cur = ch & 1;
        if (ch < 24) {
            int nxt = (ch + 1) & 1;
            int k1 = (ch + 1) * 32;
#pragma unroll
            for (int l = 0; l < 2; l++) {
                int idx = t + l * 256;
                int r = idx >> 3, kq = (idx & 7) << 2;
                cpa16(&S.As[nxt][r][kq], &Pg[(size_t)(n0 + r) * N_ + k1 + kq],
                      (n0 + r < N_) && (k1 + kq < N_));
            }
#pragma unroll
            for (int l = 0; l < 8; l++) {
                int idx = t + l * 256;
                int r = idx >> 6, cq = (idx & 63) << 2;
                cpa16(&S.Bs[nxt][r][cq], &Vt[(size_t)(k1 + r) * NB_ + cq], k1 + r < N_);
            }
            cpa_commit();
            asm volatile("cp.async.wait_group 1;\n" ::: "memory");
        } else {
            asm volatile("cp.async.wait_group 0;\n" ::: "memory");
        }
        __syncthreads();

#pragma unroll
        for (int kk = 0; kk < 4; kk++) {
            int K0 = kk * 8;
            unsigned a[4][4];
#pragma unroll
            for (int mi = 0; mi < 4; mi++) {
                int rb = mi * 16 + ly;
                a[mi][0] = S.As[cur][rb][K0 + lx];
                a[mi][1] = S.As[cur][rb + 8][K0 + lx];
                a[mi][2] = S.As[cur][rb][K0 + lx + 4];
                a[mi][3] = S.As[cur][rb + 8][K0 + lx + 4];
            }
#pragma unroll
            for (int nt = 0; nt < 4; nt++) {
                int col = w * 32 + nt * 8 + ly;
                unsigned b0 = S.Bs[cur][K0 + lx][col];
                unsigned b1 = S.Bs[cur][K0 + lx + 4][col];
#pragma unroll
                for (int mi = 0; mi < 4; mi++)
                    mma8(acc[mi][nt], a[mi][0], a[mi][1], a[mi][2], a[mi][3], b0, b1);
            }
        }
        __syncthreads();
    }

    // epilogue: g_posout[b][n][h*32+d] = gate * acc
#pragma unroll
    for (int mi = 0; mi < 4; mi++) {
        int r0 = n0 + mi * 16 + ly;
        int r1 = r0 + 8;
#pragma unroll
        for (int nt = 0; nt < 4; nt++) {
            int col = w * 32 + nt * 8 + lx * 2;
            int bb = col >> 5, d = col & 31;
            if (r0 < N_) {
                float2 v; v.x = acc[mi][nt].x * gate; v.y = acc[mi][nt].y * gate;
                *(float2*)&g_posout[((size_t)bb * N_ + r0) * DIM_ + h * HD_ + d] = v;
            }
            if (r1 < N_) {
                float2 v; v.x = acc[mi][nt].z * gate; v.y = acc[mi][nt].w * gate;
                *(float2*)&g_posout[((size_t)bb * N_ + r1) * DIM_ + h * HD_ + d] = v;
            }
        }
    }
}

// ---------------------------------------------------------------------------
// Kernel 3: fused gated patch attention (pos path precomputed by pos_pv).
// Writes g_att as tf32 bits for gemm_out's cp.async.
// ---------------------------------------------------------------------------
#define QSTR 36
#define VSTR 40
#define PSTR 68
struct ASmem {
    unsigned Qs[64][QSTR];
    unsigned P1[64][PSTR];
    unsigned Ks[2][64][QSTR];
    unsigned Vs[2][64][VSTR];
};

__global__ __launch_bounds__(128) void attn_kernel(const float* __restrict__ gating) {
    extern __shared__ char sraw[];
    ASmem& S = *reinterpret_cast<ASmem*>(sraw);

    int t = threadIdx.x, w = t >> 5, lane = t & 31;
    int ly = lane >> 2, lx = lane & 3;
    int bh = blockIdx.y;
    int b = bh / H_, h = bh - b * H_;
    int q0 = blockIdx.x * 64;
    int R0 = w * 16;

    const float* Qg = g_q + (size_t)bh * N_ * HD_;
    const float* Kg = g_k + (size_t)bh * N_ * HD_;
    const float* Vg = g_v + (size_t)bh * N_ * HD_;

    float gate = 1.f / (1.f + __expf(-gating[h]));

    // prologue: Q + iter-0 tiles
#pragma unroll
    for (int l = 0; l < 4; l++) {
        int idx = t + l * 128;
        int r = idx >> 3, dq = (idx & 7) << 2;
        cpa16(&S.Qs[r][dq], &Qg[(size_t)(q0 + r) * HD_ + dq], q0 + r < N_);
    }
#pragma unroll
    for (int l = 0; l < 4; l++) {
        int idx = t + l * 128;
        int r = idx >> 3, dq = (idx & 7) << 2;
        bool mv = r < N_;
        cpa16(&S.Ks[0][r][dq], &Kg[(size_t)r * HD_ + dq], mv);
        cpa16(&S.Vs[0][r][dq], &Vg[(size_t)r * HD_ + dq], mv);
    }
    cpa_commit();

    float4 opat[4];
#pragma unroll
    for (int i = 0; i < 4; i++) opat[i] = make_float4(0.f, 0.f, 0.f, 0.f);
    float rs0 = 0.f, rs1 = 0.f;

    for (int it = 0; it < 13; it++) {
        int cur = it & 1;
        if (it < 12) {
            int nxt = (it + 1) & 1;
            int m1 = (it + 1) * 64;
#pragma unroll
            for (int l = 0; l < 4; l++) {
                int idx = t + l * 128;
                int r = idx >> 3, dq = (idx & 7) << 2;
                bool mv = m1 + r < N_;
                cpa16(&S.Ks[nxt][r][dq], &Kg[(size_t)(m1 + r) * HD_ + dq], mv);
                cpa16(&S.Vs[nxt][r][dq], &Vg[(size_t)(m1 + r) * HD_ + dq], mv);
            }
            cpa_commit();
            asm volatile("cp.async.wait_group 1;\n" ::: "memory");
        } else {
            asm volatile("cp.async.wait_group 0;\n" ::: "memory");
        }
        __syncthreads();

        // S = Q K^T  (16 x 64 per warp)
        float4 sacc[8];
#pragma unroll
        for (int i = 0; i < 8; i++) sacc[i] = make_float4(0.f,0.f,0.f,0.f);
#pragma unroll
        for (int kk = 0; kk < 4; kk++) {
            int K0 = kk * 8;
            unsigned a0 = S.Qs[R0 + ly][K0 + lx];
            unsigned a1 = S.Qs[R0 + ly + 8][K0 + lx];
            unsigned a2 = S.Qs[R0 + ly][K0 + lx + 4];
            unsigned a3 = S.Qs[R0 + ly + 8][K0 + lx + 4];
#pragma unroll
            for (int nt = 0; nt < 8; nt++) {
                unsigned b0 = S.Ks[cur][nt * 8 + ly][K0 + lx];
                unsigned b1 = S.Ks[cur][nt * 8 + ly][K0 + lx + 4];
                mma8(sacc[nt], a0, a1, a2, a3, b0, b1);
            }
        }

        // exp + rowsum + stage P1 (warp-private rows)
        int m0 = it * 64;
#pragma unroll
        for (int nt = 0; nt < 8; nt++) {
            int mc = m0 + nt * 8 + lx * 2;
            bool mv = (mc < N_);
            float ex = mv ? __expf(sacc[nt].x) : 0.f;
            float ey = mv ? __expf(sacc[nt].y) : 0.f;
            float ez = mv ? __expf(sacc[nt].z) : 0.f;
            float ew = mv ? __expf(sacc[nt].w) : 0.f;
            rs0 += ex + ey;
            rs1 += ez + ew;
            uint2 u01; u01.x = f2tf(ex); u01.y = f2tf(ey);
            uint2 u23; u23.x = f2tf(ez); u23.y = f2tf(ew);
            *(uint2*)&S.P1[R0 + ly][nt * 8 + lx * 2] = u01;
            *(uint2*)&S.P1[R0 + ly + 8][nt * 8 + lx * 2] = u23;
        }
        __syncwarp();

        // PV: patch accumulate (16 x 32 per warp)
#pragma unroll
        for (int kk = 0; kk < 8; kk++) {
            int K0 = kk * 8;
            unsigned p0 = S.P1[R0 + ly][K0 + lx];
            unsigned p1 = S.P1[R0 + ly + 8][K0 + lx];
            unsigned p2 = S.P1[R0 + ly][K0 + lx + 4];
            unsigned p3 = S.P1[R0 + ly + 8][K0 + lx + 4];
#pragma unroll
            for (int nt = 0; nt < 4; nt++) {
                unsigned b0 = S.Vs[cur][K0 + lx][nt * 8 + ly];
                unsigned b1 = S.Vs[cur][K0 + lx + 4][nt * 8 + ly];
                mma8(opat[nt], p0, p1, p2, p3, b0, b1);
            }
        }
        __syncthreads();
    }

    // rowsum reduce over the quad (lanes sharing a row)
    rs0 += __shfl_xor_sync(0xffffffffu, rs0, 1);
    rs0 += __shfl_xor_sync(0xffffffffu, rs0, 2);
    rs1 += __shfl_xor_sync(0xffffffffu, rs1, 1);
    rs1 += __shfl_xor_sync(0xffffffffu, rs1, 2);
    float inv0 = (1.f - gate) / rs0;
    float inv1 = (1.f - gate) / rs1;

    // epilogue: out = (1-g)/rowsum * O_patch + gate*O_pos; write tf32 bits
    int n0r = q0 + R0 + ly;
    int n1r = n0r + 8;
#pragma unroll
    for (int nt = 0; nt < 4; nt++) {
        int d = nt * 8 + lx * 2;
        if (n0r < N_) {
            float2 pc = *(const float2*)&g_posout[((size_t)b * N_ + n0r) * DIM_ + h * HD_ + d];
            float2 o;
            o.x = __uint_as_float(f2tf(opat[nt].x * inv0 + pc.x));
            o.y = __uint_as_float(f2tf(opat[nt].y * inv0 + pc.y));
            *(float2*)&g_att[((size_t)b * N_ + n0r) * DIM_ + h * HD_ + d] = o;
        }
        if (n1r < N_) {
            float2 pc = *(const float2*)&g_posout[((size_t)b * N_ + n1r) * DIM_ + h * HD_ + d];
            float2 o;
            o.x = __uint_as_float(f2tf(opat[nt].z * inv1 + pc.x));
            o.y = __uint_as_float(f2tf(opat[nt].w * inv1 + pc.y));
            *(float2*)&g_att[((size_t)b * N_ + n1r) * DIM_ + h * HD_ + d] = o;
        }
    }
}

// ---------------------------------------------------------------------------
extern "C" void kernel_launch(void* const* d_in, const int* in_sizes, int n_in,
                              void* d_out, int out_size) {
    const float* x      = (const float*)d_in[0];
    const float* Wq     = (const float*)d_in[1];
    const float* Wk     = (const float*)d_in[2];
    const float* Wv     = (const float*)d_in[3];
    const float* W_pos  = (const float*)d_in[4];
    const float* b_pos  = (const float*)d_in[5];
    const float* W_out  = (const float*)d_in[6];
    const float* b_out  = (const float*)d_in[7];
    const float* gating = (const float*)d_in[8];
    float* out = (float*)d_out;

    cudaFuncSetAttribute(attn_kernel, cudaFuncAttributeMaxDynamicSharedMemorySize,
                         (int)sizeof(ASmem));
    cudaFuncSetAttribute(pos_pv, cudaFuncAttributeMaxDynamicSharedMemorySize,
                         (int)sizeof(PPSmem));

    cvt_kernel<<<512, 256>>>(x, Wq, Wk, Wv, W_out);
    pos_kernel<<<H_ * N_, 256>>>(W_pos, b_pos);

    gemm_qkv<<<dim3(3 * DIM_ / 64, ROWS_ / 64), 128>>>();                 // (18, 98)

    pos_pv<<<dim3(13, H_), 256, sizeof(PPSmem)>>>(gating);                // (13, 12)

    attn_kernel<<<dim3(13, B_ * H_), 128, sizeof(ASmem)>>>(gating);

    gemm_out<<<dim3(DIM_ / 64, ROWS_ / 64), 128>>>(b_out, out);           // (6, 98)
}

// round 7
// speedup vs baseline: 1.0840x; 1.0840x over previous
#include <cuda_runtime.h>
#include <cstdint>

#define B_   8
#define N_   784
#define DIM_ 384
#define H_   12
#define HD_  32
#define GS_  28
#define ROWS_ (B_*N_)   // 6272
#define SCALE_ 0.28867513459481287f   // 12^-0.5

// Scratch (allocation-free rule: __device__ globals)
// g_q/g_k/g_v/g_pos hold tf32 bit patterns (producers pre-convert).
__device__ float g_q[B_*H_*N_*HD_];
__device__ float g_k[B_*H_*N_*HD_];
__device__ float g_v[B_*H_*N_*HD_];
__device__ float g_att[B_*N_*DIM_];      // attn output, fp32
__device__ float g_pos[H_*N_*N_];        // normalized positional scores (tf32 bits)

// ---------------------------------------------------------------------------
// helpers
// ---------------------------------------------------------------------------
__device__ __forceinline__ unsigned f2tf(float f) {
    unsigned r; asm("cvt.rna.tf32.f32 %0, %1;" : "=r"(r) : "f"(f)); return r;
}
__device__ __forceinline__ void mma8(float4& d,
                                     unsigned a0, unsigned a1, unsigned a2, unsigned a3,
                                     unsigned b0, unsigned b1) {
    asm volatile("mma.sync.aligned.m16n8k8.row.col.f32.tf32.tf32.f32 "
                 "{%0,%1,%2,%3}, {%4,%5,%6,%7}, {%8,%9}, {%0,%1,%2,%3};\n"
                 : "+f"(d.x), "+f"(d.y), "+f"(d.z), "+f"(d.w)
                 : "r"(a0), "r"(a1), "r"(a2), "r"(a3), "r"(b0), "r"(b1));
}
__device__ __forceinline__ void cpa16(void* s, const void* g, bool pred) {
    unsigned sa = (unsigned)__cvta_generic_to_shared(s);
    int sz = pred ? 16 : 0;
    asm volatile("cp.async.cg.shared.global [%0], [%1], 16, %2;\n"
                 :: "r"(sa), "l"(g), "r"(sz) : "memory");
}
__device__ __forceinline__ void cpa_commit() {
    asm volatile("cp.async.commit_group;\n" ::: "memory");
}

// ---------------------------------------------------------------------------
// Kernel 1: normalized positional softmax  pos[h][n][m]  (writes tf32 bits)
// ---------------------------------------------------------------------------
__global__ void pos_kernel(const float* __restrict__ W_pos,
                           const float* __restrict__ b_pos) {
    int hn = blockIdx.x;
    int h = hn / N_, n = hn - h * N_;
    int nx = n % GS_, ny = n / GS_;
    float w0 = W_pos[h*3+0], w1 = W_pos[h*3+1], w2 = W_pos[h*3+2], bp = b_pos[h];
    int t = threadIdx.x;

    float lg[4];
    float lmax = -1e30f;
#pragma unroll
    for (int i = 0; i < 4; i++) {
        int m = t + i * 256;
        if (m < N_) {
            int mx = m % GS_, my = m / GS_;
            float dx = (float)(mx - nx), dy = (float)(my - ny);
            float v = fmaf(w2, dx*dx + dy*dy, fmaf(w1, dy, fmaf(w0, dx, bp)));
            lg[i] = v;
            lmax = fmaxf(lmax, v);
        } else lg[i] = -1e30f;
    }
    __shared__ float sred[8];
    __shared__ float ssum[8];
#pragma unroll
    for (int o = 16; o > 0; o >>= 1)
        lmax = fmaxf(lmax, __shfl_xor_sync(0xffffffffu, lmax, o));
    if ((t & 31) == 0) sred[t >> 5] = lmax;
    __syncthreads();
    float bmax = fmaxf(fmaxf(fmaxf(sred[0], sred[1]), fmaxf(sred[2], sred[3])),
                       fmaxf(fmaxf(sred[4], sred[5]), fmaxf(sred[6], sred[7])));

    float e[4]; float lsum = 0.f;
#pragma unroll
    for (int i = 0; i < 4; i++) { e[i] = __expf(lg[i] - bmax); lsum += e[i]; }
#pragma unroll
    for (int o = 16; o > 0; o >>= 1)
        lsum += __shfl_xor_sync(0xffffffffu, lsum, o);
    if ((t & 31) == 0) ssum[t >> 5] = lsum;
    __syncthreads();
    float tot = ((ssum[0]+ssum[1])+(ssum[2]+ssum[3]))+((ssum[4]+ssum[5])+(ssum[6]+ssum[7]));
    float inv = 1.f / tot;

    float* outp = g_pos + (size_t)hn * N_;
#pragma unroll
    for (int i = 0; i < 4; i++) {
        int m = t + i * 256;
        if (m < N_) outp[m] = __uint_as_float(f2tf(e[i] * inv));
    }
}

// ---------------------------------------------------------------------------
// Kernel 2: fused QKV tf32 GEMM, reg-prefetch pipelined (L1-friendly LDG).
// 128x64 tile, 256 threads (8 warps as 4x2). Column space 1152 = [Wq|Wk|Wv].
// Writes tf32 bits (Q pre-scaled) in [b][h][n][d] layout.
// ---------------------------------------------------------------------------
#define GSTR 36
struct GSmem {
    unsigned Xs[2][128][GSTR];
    unsigned Ws[2][64][GSTR];
};

__global__ __launch_bounds__(256) void gemm_qkv(
    const float* __restrict__ X, const float* __restrict__ Wq,
    const float* __restrict__ Wk, const float* __restrict__ Wv)
{
    extern __shared__ char sraw[];
    GSmem& S = *reinterpret_cast<GSmem*>(sraw);

    int t = threadIdx.x, w = t >> 5, lane = t & 31;
    int ly = lane >> 2, lx = lane & 3;
    int wr = w >> 1, wc = w & 1;
    int row0 = blockIdx.y * 128, col0 = blockIdx.x * 64;
    int wsel = col0 / DIM_;
    int colw = col0 - wsel * DIM_;
    const float* W = (wsel == 0) ? Wq : (wsel == 1) ? Wk : Wv;
    float* Op = (wsel == 0) ? g_q : (wsel == 1) ? g_k : g_v;
    float scale = (wsel == 0) ? SCALE_ : 1.f;

    float4 rx[4], rw[2];
#pragma unroll
    for (int l = 0; l < 4; l++) {
        int idx = t + l * 256;
        int r = idx >> 3, kq = (idx & 7) << 2;
        rx[l] = *(const float4*)&X[(size_t)(row0 + r) * DIM_ + kq];
    }
#pragma unroll
    for (int l = 0; l < 2; l++) {
        int idx = t + l * 256;
        int r = idx >> 3, kq = (idx & 7) << 2;
        rw[l] = *(const float4*)&W[(size_t)(colw + r) * DIM_ + kq];
    }
#pragma unroll
    for (int l = 0; l < 4; l++) {
        int idx = t + l * 256;
        int r = idx >> 3, kq = (idx & 7) << 2;
        *(uint4*)&S.Xs[0][r][kq] = make_uint4(f2tf(rx[l].x), f2tf(rx[l].y), f2tf(rx[l].z), f2tf(rx[l].w));
    }
#pragma unroll
    for (int l = 0; l < 2; l++) {
        int idx = t + l * 256;
        int r = idx >> 3, kq = (idx & 7) << 2;
        *(uint4*)&S.Ws[0][r][kq] = make_uint4(f2tf(rw[l].x), f2tf(rw[l].y), f2tf(rw[l].z), f2tf(rw[l].w));
    }
    __syncthreads();

    float4 acc[2][4];
#pragma unroll
    for (int i = 0; i < 2; i++)
#pragma unroll
        for (int j = 0; j < 4; j++) acc[i][j] = make_float4(0.f, 0.f, 0.f, 0.f);

    for (int ki = 0; ki < 12; ki++) {
        int cur = ki & 1;
        if (ki < 11) {
            int k0 = (ki + 1) * 32;
#pragma unroll
            for (int l = 0; l < 4; l++) {
                int idx = t + l * 256;
                int r = idx >> 3, kq = (idx & 7) << 2;
                rx[l] = *(const float4*)&X[(size_t)(row0 + r) * DIM_ + k0 + kq];
            }
#pragma unroll
            for (int l = 0; l < 2; l++) {
                int idx = t + l * 256;
                int r = idx >> 3, kq = (idx & 7) << 2;
                rw[l] = *(const float4*)&W[(size_t)(colw + r) * DIM_ + k0 + kq];
            }
        }
#pragma unroll
        for (int kk = 0; kk < 4; kk++) {
            int K0 = kk * 8;
            unsigned a[2][4];
#pragma unroll
            for (int mi = 0; mi < 2; mi++) {
                int rb = wr * 32 + mi * 16 + ly;
                a[mi][0] = S.Xs[cur][rb][K0 + lx];
                a[mi][1] = S.Xs[cur][rb + 8][K0 + lx];
                a[mi][2] = S.Xs[cur][rb][K0 + lx + 4];
                a[mi][3] = S.Xs[cur][rb + 8][K0 + lx + 4];
            }
#pragma unroll
            for (int nt = 0; nt < 4; nt++) {
                int cb = wc * 32 + nt * 8 + ly;
                unsigned b0 = S.Ws[cur][cb][K0 + lx];
                unsigned b1 = S.Ws[cur][cb][K0 + lx + 4];
                mma8(acc[0][nt], a[0][0], a[0][1], a[0][2], a[0][3], b0, b1);
                mma8(acc[1][nt], a[1][0], a[1][1], a[1][2], a[1][3], b0, b1);
            }
        }
        if (ki < 11) {
            int nxt = (ki + 1) & 1;
#pragma unroll
            for (int l = 0; l < 4; l++) {
                int idx = t + l * 256;
                int r = idx >> 3, kq = (idx & 7) << 2;
                *(uint4*)&S.Xs[nxt][r][kq] = make_uint4(f2tf(rx[l].x), f2tf(rx[l].y), f2tf(rx[l].z), f2tf(rx[l].w));
            }
#pragma unroll
            for (int l = 0; l < 2; l++) {
                int idx = t + l * 256;
                int r = idx >> 3, kq = (idx & 7) << 2;
                *(uint4*)&S.Ws[nxt][r][kq] = make_uint4(f2tf(rw[l].x), f2tf(rw[l].y), f2tf(rw[l].z), f2tf(rw[l].w));
            }
        }
        __syncthreads();
    }

    // epilogue: write tf32 bits, [b][h][n][d] layout, Q pre-scaled
    int h = (colw + wc * 32) >> 5;
#pragma unroll
    for (int mi = 0; mi < 2; mi++) {
        int row = row0 + wr * 32 + mi * 16 + ly;
#pragma unroll
        for (int nt = 0; nt < 4; nt++) {
            int d = nt * 8 + lx * 2;
            {
                int b = row / N_, n = row - b * N_;
                float2 v;
                v.x = __uint_as_float(f2tf(acc[mi][nt].x * scale));
                v.y = __uint_as_float(f2tf(acc[mi][nt].y * scale));
                *(float2*)&Op[(((size_t)(b * H_ + h)) * N_ + n) * HD_ + d] = v;
            }
            {
                int row2 = row + 8;
                int b = row2 / N_, n = row2 - b * N_;
                float2 v;
                v.x = __uint_as_float(f2tf(acc[mi][nt].z * scale));
                v.y = __uint_as_float(f2tf(acc[mi][nt].w * scale));
                *(float2*)&Op[(((size_t)(b * H_ + h)) * N_ + n) * HD_ + d] = v;
            }
        }
    }
}

// ---------------------------------------------------------------------------
// Kernel 2b: out-projection tf32 GEMM (same 128x64 pipeline), + bias, fp32 out
// ---------------------------------------------------------------------------
__global__ __launch_bounds__(256) void gemm_out(
    const float* __restrict__ W, const float* __restrict__ bias,
    float* __restrict__ OUTp)
{
    extern __shared__ char sraw[];
    GSmem& S = *reinterpret_cast<GSmem*>(sraw);

    int t = threadIdx.x, w = t >> 5, lane = t & 31;
    int ly = lane >> 2, lx = lane & 3;
    int wr = w >> 1, wc = w & 1;
    int row0 = blockIdx.y * 128, col0 = blockIdx.x * 64;
    const float* X = g_att;

    float4 rx[4], rw[2];
#pragma unroll
    for (int l = 0; l < 4; l++) {
        int idx = t + l * 256;
        int r = idx >> 3, kq = (idx & 7) << 2;
        rx[l] = *(const float4*)&X[(size_t)(row0 + r) * DIM_ + kq];
    }
#pragma unroll
    for (int l = 0; l < 2; l++) {
        int idx = t + l * 256;
        int r = idx >> 3, kq = (idx & 7) << 2;
        rw[l] = *(const float4*)&W[(size_t)(col0 + r) * DIM_ + kq];
    }
#pragma unroll
    for (int l = 0; l < 4; l++) {
        int idx = t + l * 256;
        int r = idx >> 3, kq = (idx & 7) << 2;
        *(uint4*)&S.Xs[0][r][kq] = make_uint4(f2tf(rx[l].x), f2tf(rx[l].y), f2tf(rx[l].z), f2tf(rx[l].w));
    }
#pragma unroll
    for (int l = 0; l < 2; l++) {
        int idx = t + l * 256;
        int r = idx >> 3, kq = (idx & 7) << 2;
        *(uint4*)&S.Ws[0][r][kq] = make_uint4(f2tf(rw[l].x), f2tf(rw[l].y), f2tf(rw[l].z), f2tf(rw[l].w));
    }
    __syncthreads();

    float4 acc[2][4];
#pragma unroll
    for (int i = 0; i < 2; i++)
#pragma unroll
        for (int j = 0; j < 4; j++) acc[i][j] = make_float4(0.f, 0.f, 0.f, 0.f);

    for (int ki = 0; ki < 12; ki++) {
        int cur = ki & 1;
        if (ki < 11) {
            int k0 = (ki + 1) * 32;
#pragma unroll
            for (int l = 0; l < 4; l++) {
                int idx = t + l * 256;
                int r = idx >> 3, kq = (idx & 7) << 2;
                rx[l] = *(const float4*)&X[(size_t)(row0 + r) * DIM_ + k0 + kq];
            }
#pragma unroll
            for (int l = 0; l < 2; l++) {
                int idx = t + l * 256;
                int r = idx >> 3, kq = (idx & 7) << 2;
                rw[l] = *(const float4*)&W[(size_t)(col0 + r) * DIM_ + k0 + kq];
            }
        }
#pragma unroll
        for (int kk = 0; kk < 4; kk++) {
            int K0 = kk * 8;
            unsigned a[2][4];
#pragma unroll
            for (int mi = 0; mi < 2; mi++) {
                int rb = wr * 32 + mi * 16 + ly;
                a[mi][0] = S.Xs[cur][rb][K0 + lx];
                a[mi][1] = S.Xs[cur][rb + 8][K0 + lx];
                a[mi][2] = S.Xs[cur][rb][K0 + lx + 4];
                a[mi][3] = S.Xs[cur][rb + 8][K0 + lx + 4];
            }
#pragma unroll
            for (int nt = 0; nt < 4; nt++) {
                int cb = wc * 32 + nt * 8 + ly;
                unsigned b0 = S.Ws[cur][cb][K0 + lx];
                unsigned b1 = S.Ws[cur][cb][K0 + lx + 4];
                mma8(acc[0][nt], a[0][0], a[0][1], a[0][2], a[0][3], b0, b1);
                mma8(acc[1][nt], a[1][0], a[1][1], a[1][2], a[1][3], b0, b1);
            }
        }
        if (ki < 11) {
            int nxt = (ki + 1) & 1;
#pragma unroll
            for (int l = 0; l < 4; l++) {
                int idx = t + l * 256;
                int r = idx >> 3, kq = (idx & 7) << 2;
                *(uint4*)&S.Xs[nxt][r][kq] = make_uint4(f2tf(rx[l].x), f2tf(rx[l].y), f2tf(rx[l].z), f2tf(rx[l].w));
            }
#pragma unroll
            for (int l = 0; l < 2; l++) {
                int idx = t + l * 256;
                int r = idx >> 3, kq = (idx & 7) << 2;
                *(uint4*)&S.Ws[nxt][r][kq] = make_uint4(f2tf(rw[l].x), f2tf(rw[l].y), f2tf(rw[l].z), f2tf(rw[l].w));
            }
        }
        __syncthreads();
    }

#pragma unroll
    for (int mi = 0; mi < 2; mi++) {
        int row = row0 + wr * 32 + mi * 16 + ly;
#pragma unroll
        for (int nt = 0; nt < 4; nt++) {
            int col = col0 + wc * 32 + nt * 8 + lx * 2;
            float b0 = bias[col], b1 = bias[col + 1];
            float2 v0; v0.x = acc[mi][nt].x + b0; v0.y = acc[mi][nt].y + b1;
            *(float2*)&OUTp[(size_t)row * DIM_ + col] = v0;
            float2 v1; v1.x = acc[mi][nt].z + b0; v1.y = acc[mi][nt].w + b1;
            *(float2*)&OUTp[(size_t)(row + 8) * DIM_ + col] = v1;
        }
    }
}

// ---------------------------------------------------------------------------
// Kernel 3: fused gated attention, cp.async double-buffered mainloop.
// Dual PV accumulation (patch + pos). Champion round-4 structure.
// ---------------------------------------------------------------------------
#define QSTR 36
#define VSTR 40
#define PSTR 68
struct ASmem {
    unsigned Qs[64][QSTR];
    unsigned P1[64][PSTR];
    unsigned Ks[2][64][QSTR];
    unsigned Vs[2][64][VSTR];
    unsigned P2[2][64][PSTR];
};

__global__ __launch_bounds__(128) void attn_kernel(const float* __restrict__ gating) {
    extern __shared__ char sraw[];
    ASmem& S = *reinterpret_cast<ASmem*>(sraw);

    int t = threadIdx.x, w = t >> 5, lane = t & 31;
    int ly = lane >> 2, lx = lane & 3;
    int bh = blockIdx.y;
    int b = bh / H_, h = bh - b * H_;
    int q0 = blockIdx.x * 64;
    int R0 = w * 16;

    const float* Qg   = g_q + (size_t)bh * N_ * HD_;
    const float* Kg   = g_k + (size_t)bh * N_ * HD_;
    const float* Vg   = g_v + (size_t)bh * N_ * HD_;
    const float* POSg = g_pos + (size_t)h * N_ * N_;

    float gate = 1.f / (1.f + __expf(-gating[h]));

    // prologue: Q + iter-0 tiles, one commit group
#pragma unroll
    for (int l = 0; l < 4; l++) {
        int idx = t + l * 128;
        int r = idx >> 3, dq = (idx & 7) << 2;
        cpa16(&S.Qs[r][dq], &Qg[(size_t)(q0 + r) * HD_ + dq], q0 + r < N_);
    }
#pragma unroll
    for (int l = 0; l < 4; l++) {
        int idx = t + l * 128;
        int r = idx >> 3, dq = (idx & 7) << 2;
        bool mv = r < N_;   // m0 = 0
        cpa16(&S.Ks[0][r][dq], &Kg[(size_t)r * HD_ + dq], mv);
        cpa16(&S.Vs[0][r][dq], &Vg[(size_t)r * HD_ + dq], mv);
    }
#pragma unroll
    for (int l = 0; l < 8; l++) {
        int idx = t + l * 128;
        int r = idx >> 4, cq = (idx & 15) << 2;
        cpa16(&S.P2[0][r][cq], &POSg[(size_t)(q0 + r) * N_ + cq], (q0 + r < N_) && (cq < N_));
    }
    cpa_commit();

    float4 opat[4], opos[4];
#pragma unroll
    for (int i = 0; i < 4; i++) { opat[i] = make_float4(0.f,0.f,0.f,0.f); opos[i] = opat[i]; }
    float rs0 = 0.f, rs1 = 0.f;

    for (int it = 0; it < 13; it++) {
        int cur = it & 1;
        if (it < 12) {
            int nxt = (it + 1) & 1;
            int m1 = (it + 1) * 64;
#pragma unroll
            for (int l = 0; l < 4; l++) {
                int idx = t + l * 128;
                int r = idx >> 3, dq = (idx & 7) << 2;
                bool mv = m1 + r < N_;
                cpa16(&S.Ks[nxt][r][dq], &Kg[(size_t)(m1 + r) * HD_ + dq], mv);
                cpa16(&S.Vs[nxt][r][dq], &Vg[(size_t)(m1 + r) * HD_ + dq], mv);
            }
#pragma unroll
            for (int l = 0; l < 8; l++) {
                int idx = t + l * 128;
                int r = idx >> 4, cq = (idx & 15) << 2;
                cpa16(&S.P2[nxt][r][cq], &POSg[(size_t)(q0 + r) * N_ + m1 + cq],
                      (q0 + r < N_) && (m1 + cq < N_));
            }
            cpa_commit();
            asm volatile("cp.async.wait_group 1;\n" ::: "memory");
        } else {
            asm volatile("cp.async.wait_group 0;\n" ::: "memory");
        }
        __syncthreads();

        // S = Q K^T  (16 x 64 per warp)
        float4 sacc[8];
#pragma unroll
        for (int i = 0; i < 8; i++) sacc[i] = make_float4(0.f,0.f,0.f,0.f);
#pragma unroll
        for (int kk = 0; kk < 4; kk++) {
            int K0 = kk * 8;
            unsigned a0 = S.Qs[R0 + ly][K0 + lx];
            unsigned a1 = S.Qs[R0 + ly + 8][K0 + lx];
            unsigned a2 = S.Qs[R0 + ly][K0 + lx + 4];
            unsigned a3 = S.Qs[R0 + ly + 8][K0 + lx + 4];
#pragma unroll
            for (int nt = 0; nt < 8; nt++) {
                unsigned b0 = S.Ks[cur][nt * 8 + ly][K0 + lx];
                unsigned b1 = S.Ks[cur][nt * 8 + ly][K0 + lx + 4];
                mma8(sacc[nt], a0, a1, a2, a3, b0, b1);
            }
        }

        // exp + rowsum + stage P1 (warp-private rows)
        int m0 = it * 64;
#pragma unroll
        for (int nt = 0; nt < 8; nt++) {
            int mc = m0 + nt * 8 + lx * 2;
            bool mv = (mc < N_);
            float ex = mv ? __expf(sacc[nt].x) : 0.f;
            float ey = mv ? __expf(sacc[nt].y) : 0.f;
            float ez = mv ? __expf(sacc[nt].z) : 0.f;
            float ew = mv ? __expf(sacc[nt].w) : 0.f;
            rs0 += ex + ey;
            rs1 += ez + ew;
            uint2 u01; u01.x = f2tf(ex); u01.y = f2tf(ey);
            uint2 u23; u23.x = f2tf(ez); u23.y = f2tf(ew);
            *(uint2*)&S.P1[R0 + ly][nt * 8 + lx * 2] = u01;
            *(uint2*)&S.P1[R0 + ly + 8][nt * 8 + lx * 2] = u23;
        }
        __syncwarp();

        // PV: dual accumulate (16 x 32 per warp)
#pragma unroll
        for (int kk = 0; kk < 8; kk++) {
            int K0 = kk * 8;
            unsigned p0 = S.P1[R0 + ly][K0 + lx];
            unsigned p1 = S.P1[R0 + ly + 8][K0 + lx];
            unsigned p2 = S.P1[R0 + ly][K0 + lx + 4];
            unsigned p3 = S.P1[R0 + ly + 8][K0 + lx + 4];
            unsigned c0 = S.P2[cur][R0 + ly][K0 + lx];
            unsigned c1 = S.P2[cur][R0 + ly + 8][K0 + lx];
            unsigned c2 = S.P2[cur][R0 + ly][K0 + lx + 4];
            unsigned c3 = S.P2[cur][R0 + ly + 8][K0 + lx + 4];
#pragma unroll
            for (int nt = 0; nt < 4; nt++) {
                unsigned b0 = S.Vs[cur][K0 + lx][nt * 8 + ly];
                unsigned b1 = S.Vs[cur][K0 + lx + 4][nt * 8 + ly];
                mma8(opat[nt], p0, p1, p2, p3, b0, b1);
                mma8(opos[nt], c0, c1, c2, c3, b0, b1);
            }
        }
        __syncthreads();   // all reads of buf[cur] done before it is refilled
    }

    // rowsum reduce over the quad (lanes sharing a row)
    rs0 += __shfl_xor_sync(0xffffffffu, rs0, 1);
    rs0 += __shfl_xor_sync(0xffffffffu, rs0, 2);
    rs1 += __shfl_xor_sync(0xffffffffu, rs1, 1);
    rs1 += __shfl_xor_sync(0xffffffffu, rs1, 2);
    float inv0 = (1.f - gate) / rs0;
    float inv1 = (1.f - gate) / rs1;

    // epilogue: out = (1-g)/rowsum * O_patch + g * O_pos (attn sums to 1)
    int n0r = q0 + R0 + ly;
    int n1r = n0r + 8;
#pragma unroll
    for (int nt = 0; nt < 4; nt++) {
        int d = nt * 8 + lx * 2;
        if (n0r < N_) {
            float2 o;
            o.x = opat[nt].x * inv0 + gate * opos[nt].x;
            o.y = opat[nt].y * inv0 + gate * opos[nt].y;
            *(float2*)&g_att[((size_t)b * N_ + n0r) * DIM_ + h * HD_ + d] = o;
        }
        if (n1r < N_) {
            float2 o;
            o.x = opat[nt].z * inv1 + gate * opos[nt].z;
            o.y = opat[nt].w * inv1 + gate * opos[nt].w;
            *(float2*)&g_att[((size_t)b * N_ + n1r) * DIM_ + h * HD_ + d] = o;
        }
    }
}

// ---------------------------------------------------------------------------
extern "C" void kernel_launch(void* const* d_in, const int* in_sizes, int n_in,
                              void* d_out, int out_size) {
    const float* x      = (const float*)d_in[0];
    const float* Wq     = (const float*)d_in[1];
    const float* Wk     = (const float*)d_in[2];
    const float* Wv     = (const float*)d_in[3];
    const float* W_pos  = (const float*)d_in[4];
    const float* b_pos  = (const float*)d_in[5];
    const float* W_out  = (const float*)d_in[6];
    const float* b_out  = (const float*)d_in[7];
    const float* gating = (const float*)d_in[8];
    float* out = (float*)d_out;

    cudaFuncSetAttribute(attn_kernel, cudaFuncAttributeMaxDynamicSharedMemorySize,
                         (int)sizeof(ASmem));
    cudaFuncSetAttribute(gemm_qkv, cudaFuncAttributeMaxDynamicSharedMemorySize,
                         (int)sizeof(GSmem));
    cudaFuncSetAttribute(gemm_out, cudaFuncAttributeMaxDynamicSharedMemorySize,
                         (int)sizeof(GSmem));

    pos_kernel<<<H_ * N_, 256>>>(W_pos, b_pos);

    gemm_qkv<<<dim3(3 * DIM_ / 64, ROWS_ / 128), 256, sizeof(GSmem)>>>(x, Wq, Wk, Wv);  // (18, 49)

    attn_kernel<<<dim3(13, B_ * H_), 128, sizeof(ASmem)>>>(gating);

    gemm_out<<<dim3(DIM_ / 64, ROWS_ / 128), 256, sizeof(GSmem)>>>(W_out, b_out, out);  // (6, 49)
}

// round 8
// speedup vs baseline: 1.7464x; 1.6110x over previous
#include <cuda_runtime.h>
#include <cstdint>

#define B_   8
#define N_   784
#define DIM_ 384
#define H_   12
#define HD_  32
#define GS_  28
#define ROWS_ (B_*N_)   // 6272
#define SCALE_ 0.28867513459481287f   // 12^-0.5

// Scratch (allocation-free rule: __device__ globals)
// g_q/g_k/g_v/g_pos hold tf32 bit patterns (producers pre-convert).
__device__ float g_q[B_*H_*N_*HD_];
__device__ float g_k[B_*H_*N_*HD_];
__device__ float g_v[B_*H_*N_*HD_];
__device__ float g_att[B_*N_*DIM_];      // attn output, fp32
__device__ float g_pos[H_*N_*N_];        // normalized positional scores (tf32 bits)

// ---------------------------------------------------------------------------
// helpers
// ---------------------------------------------------------------------------
__device__ __forceinline__ unsigned f2tf(float f) {
    unsigned r; asm("cvt.rna.tf32.f32 %0, %1;" : "=r"(r) : "f"(f)); return r;
}
__device__ __forceinline__ void mma8(float4& d,
                                     unsigned a0, unsigned a1, unsigned a2, unsigned a3,
                                     unsigned b0, unsigned b1) {
    asm volatile("mma.sync.aligned.m16n8k8.row.col.f32.tf32.tf32.f32 "
                 "{%0,%1,%2,%3}, {%4,%5,%6,%7}, {%8,%9}, {%0,%1,%2,%3};\n"
                 : "+f"(d.x), "+f"(d.y), "+f"(d.z), "+f"(d.w)
                 : "r"(a0), "r"(a1), "r"(a2), "r"(a3), "r"(b0), "r"(b1));
}
__device__ __forceinline__ void cpa16(void* s, const void* g, bool pred) {
    unsigned sa = (unsigned)__cvta_generic_to_shared(s);
    int sz = pred ? 16 : 0;
    asm volatile("cp.async.cg.shared.global [%0], [%1], 16, %2;\n"
                 :: "r"(sa), "l"(g), "r"(sz) : "memory");
}
__device__ __forceinline__ void cpa_commit() {
    asm volatile("cp.async.commit_group;\n" ::: "memory");
}

// ---------------------------------------------------------------------------
// Kernel 1: normalized positional softmax  pos[h][n][m]  (writes tf32 bits)
// ---------------------------------------------------------------------------
__global__ void pos_kernel(const float* __restrict__ W_pos,
                           const float* __restrict__ b_pos) {
    int hn = blockIdx.x;
    int h = hn / N_, n = hn - h * N_;
    int nx = n % GS_, ny = n / GS_;
    float w0 = W_pos[h*3+0], w1 = W_pos[h*3+1], w2 = W_pos[h*3+2], bp = b_pos[h];
    int t = threadIdx.x;

    float lg[4];
    float lmax = -1e30f;
#pragma unroll
    for (int i = 0; i < 4; i++) {
        int m = t + i * 256;
        if (m < N_) {
            int mx = m % GS_, my = m / GS_;
            float dx = (float)(mx - nx), dy = (float)(my - ny);
            float v = fmaf(w2, dx*dx + dy*dy, fmaf(w1, dy, fmaf(w0, dx, bp)));
            lg[i] = v;
            lmax = fmaxf(lmax, v);
        } else lg[i] = -1e30f;
    }
    __shared__ float sred[8];
    __shared__ float ssum[8];
#pragma unroll
    for (int o = 16; o > 0; o >>= 1)
        lmax = fmaxf(lmax, __shfl_xor_sync(0xffffffffu, lmax, o));
    if ((t & 31) == 0) sred[t >> 5] = lmax;
    __syncthreads();
    float bmax = fmaxf(fmaxf(fmaxf(sred[0], sred[1]), fmaxf(sred[2], sred[3])),
                       fmaxf(fmaxf(sred[4], sred[5]), fmaxf(sred[6], sred[7])));

    float e[4]; float lsum = 0.f;
#pragma unroll
    for (int i = 0; i < 4; i++) { e[i] = __expf(lg[i] - bmax); lsum += e[i]; }
#pragma unroll
    for (int o = 16; o > 0; o >>= 1)
        lsum += __shfl_xor_sync(0xffffffffu, lsum, o);
    if ((t & 31) == 0) ssum[t >> 5] = lsum;
    __syncthreads();
    float tot = ((ssum[0]+ssum[1])+(ssum[2]+ssum[3]))+((ssum[4]+ssum[5])+(ssum[6]+ssum[7]));
    float inv = 1.f / tot;

    float* outp = g_pos + (size_t)hn * N_;
#pragma unroll
    for (int i = 0; i < 4; i++) {
        int m = t + i * 256;
        if (m < N_) outp[m] = __uint_as_float(f2tf(e[i] * inv));
    }
}

// ---------------------------------------------------------------------------
// Kernel 2: fused QKV tf32 GEMM (round-4 champion config: 64x64, 128 thr,
// LDG reg-prefetch pipeline). Writes tf32 bits (Q pre-scaled), [b][h][n][d].
// ---------------------------------------------------------------------------
#define GSTR 36
__global__ __launch_bounds__(128) void gemm_qkv(
    const float* __restrict__ X, const float* __restrict__ Wq,
    const float* __restrict__ Wk, const float* __restrict__ Wv)
{
    __shared__ unsigned Xs[2][64][GSTR];
    __shared__ unsigned Ws[2][64][GSTR];

    int t = threadIdx.x, w = t >> 5, lane = t & 31;
    int ly = lane >> 2, lx = lane & 3;
    int wr = w >> 1, wc = w & 1;
    int row0 = blockIdx.y * 64, col0 = blockIdx.x * 64;
    int wsel = col0 / DIM_;
    int colw = col0 - wsel * DIM_;
    const float* W = (wsel == 0) ? Wq : (wsel == 1) ? Wk : Wv;
    float* Op = (wsel == 0) ? g_q : (wsel == 1) ? g_k : g_v;
    float scale = (wsel == 0) ? SCALE_ : 1.f;

    float4 rx[4], rw[4];
#pragma unroll
    for (int l = 0; l < 4; l++) {
        int idx = t + l * 128;
        int r = idx >> 3, kq = (idx & 7) << 2;
        rx[l] = *(const float4*)&X[(size_t)(row0 + r) * DIM_ + kq];
        rw[l] = *(const float4*)&W[(size_t)(colw + r) * DIM_ + kq];
    }
#pragma unroll
    for (int l = 0; l < 4; l++) {
        int idx = t + l * 128;
        int r = idx >> 3, kq = (idx & 7) << 2;
        *(uint4*)&Xs[0][r][kq] = make_uint4(f2tf(rx[l].x), f2tf(rx[l].y), f2tf(rx[l].z), f2tf(rx[l].w));
        *(uint4*)&Ws[0][r][kq] = make_uint4(f2tf(rw[l].x), f2tf(rw[l].y), f2tf(rw[l].z), f2tf(rw[l].w));
    }
    __syncthreads();

    float4 acc[2][4];
#pragma unroll
    for (int i = 0; i < 2; i++)
#pragma unroll
        for (int j = 0; j < 4; j++) acc[i][j] = make_float4(0.f, 0.f, 0.f, 0.f);

    for (int ki = 0; ki < 12; ki++) {
        int cur = ki & 1;
        if (ki < 11) {
            int k0 = (ki + 1) * 32;
#pragma unroll
            for (int l = 0; l < 4; l++) {
                int idx = t + l * 128;
                int r = idx >> 3, kq = (idx & 7) << 2;
                rx[l] = *(const float4*)&X[(size_t)(row0 + r) * DIM_ + k0 + kq];
                rw[l] = *(const float4*)&W[(size_t)(colw + r) * DIM_ + k0 + kq];
            }
        }
#pragma unroll
        for (int kk = 0; kk < 4; kk++) {
            int K0 = kk * 8;
            unsigned a[2][4];
#pragma unroll
            for (int mi = 0; mi < 2; mi++) {
                int rb = wr * 32 + mi * 16 + ly;
                a[mi][0] = Xs[cur][rb][K0 + lx];
                a[mi][1] = Xs[cur][rb + 8][K0 + lx];
                a[mi][2] = Xs[cur][rb][K0 + lx + 4];
                a[mi][3] = Xs[cur][rb + 8][K0 + lx + 4];
            }
#pragma unroll
            for (int nt = 0; nt < 4; nt++) {
                int cb = wc * 32 + nt * 8 + ly;
                unsigned b0 = Ws[cur][cb][K0 + lx];
                unsigned b1 = Ws[cur][cb][K0 + lx + 4];
                mma8(acc[0][nt], a[0][0], a[0][1], a[0][2], a[0][3], b0, b1);
                mma8(acc[1][nt], a[1][0], a[1][1], a[1][2], a[1][3], b0, b1);
            }
        }
        if (ki < 11) {
            int nxt = (ki + 1) & 1;
#pragma unroll
            for (int l = 0; l < 4; l++) {
                int idx = t + l * 128;
                int r = idx >> 3, kq = (idx & 7) << 2;
                *(uint4*)&Xs[nxt][r][kq] = make_uint4(f2tf(rx[l].x), f2tf(rx[l].y), f2tf(rx[l].z), f2tf(rx[l].w));
                *(uint4*)&Ws[nxt][r][kq] = make_uint4(f2tf(rw[l].x), f2tf(rw[l].y), f2tf(rw[l].z), f2tf(rw[l].w));
            }
        }
        __syncthreads();
    }

    // epilogue: write tf32 bits, [b][h][n][d] layout, Q pre-scaled
    int h = (colw + wc * 32) >> 5;
#pragma unroll
    for (int mi = 0; mi < 2; mi++) {
        int row = row0 + wr * 32 + mi * 16 + ly;
#pragma unroll
        for (int nt = 0; nt < 4; nt++) {
            int d = nt * 8 + lx * 2;
            {
                int b = row / N_, n = row - b * N_;
                float2 v;
                v.x = __uint_as_float(f2tf(acc[mi][nt].x * scale));
                v.y = __uint_as_float(f2tf(acc[mi][nt].y * scale));
                *(float2*)&Op[(((size_t)(b * H_ + h)) * N_ + n) * HD_ + d] = v;
            }
            {
                int row2 = row + 8;
                int b = row2 / N_, n = row2 - b * N_;
                float2 v;
                v.x = __uint_as_float(f2tf(acc[mi][nt].z * scale));
                v.y = __uint_as_float(f2tf(acc[mi][nt].w * scale));
                *(float2*)&Op[(((size_t)(b * H_ + h)) * N_ + n) * HD_ + d] = v;
            }
        }
    }
}

// ---------------------------------------------------------------------------
// Kernel 2b: out-projection tf32 GEMM (round-4 champion config), +bias, fp32
// ---------------------------------------------------------------------------
__global__ __launch_bounds__(128) void gemm_out(
    const float* __restrict__ W, const float* __restrict__ bias,
    float* __restrict__ OUTp)
{
    __shared__ unsigned Xs[2][64][GSTR];
    __shared__ unsigned Ws[2][64][GSTR];

    int t = threadIdx.x, w = t >> 5, lane = t & 31;
    int ly = lane >> 2, lx = lane & 3;
    int wr = w >> 1, wc = w & 1;
    int row0 = blockIdx.y * 64, col0 = blockIdx.x * 64;
    const float* X = g_att;

    float4 rx[4], rw[4];
#pragma unroll
    for (int l = 0; l < 4; l++) {
        int idx = t + l * 128;
        int r = idx >> 3, kq = (idx & 7) << 2;
        rx[l] = *(const float4*)&X[(size_t)(row0 + r) * DIM_ + kq];
        rw[l] = *(const float4*)&W[(size_t)(col0 + r) * DIM_ + kq];
    }
#pragma unroll
    for (int l = 0; l < 4; l++) {
        int idx = t + l * 128;
        int r = idx >> 3, kq = (idx & 7) << 2;
        *(uint4*)&Xs[0][r][kq] = make_uint4(f2tf(rx[l].x), f2tf(rx[l].y), f2tf(rx[l].z), f2tf(rx[l].w));
        *(uint4*)&Ws[0][r][kq] = make_uint4(f2tf(rw[l].x), f2tf(rw[l].y), f2tf(rw[l].z), f2tf(rw[l].w));
    }
    __syncthreads();

    float4 acc[2][4];
#pragma unroll
    for (int i = 0; i < 2; i++)
#pragma unroll
        for (int j = 0; j < 4; j++) acc[i][j] = make_float4(0.f, 0.f, 0.f, 0.f);

    for (int ki = 0; ki < 12; ki++) {
        int cur = ki & 1;
        if (ki < 11) {
            int k0 = (ki + 1) * 32;
#pragma unroll
            for (int l = 0; l < 4; l++) {
                int idx = t + l * 128;
                int r = idx >> 3, kq = (idx & 7) << 2;
                rx[l] = *(const float4*)&X[(size_t)(row0 + r) * DIM_ + k0 + kq];
                rw[l] = *(const float4*)&W[(size_t)(col0 + r) * DIM_ + k0 + kq];
            }
        }
#pragma unroll
        for (int kk = 0; kk < 4; kk++) {
            int K0 = kk * 8;
            unsigned a[2][4];
#pragma unroll
            for (int mi = 0; mi < 2; mi++) {
                int rb = wr * 32 + mi * 16 + ly;
                a[mi][0] = Xs[cur][rb][K0 + lx];
                a[mi][1] = Xs[cur][rb + 8][K0 + lx];
                a[mi][2] = Xs[cur][rb][K0 + lx + 4];
                a[mi][3] = Xs[cur][rb + 8][K0 + lx + 4];
            }
#pragma unroll
            for (int nt = 0; nt < 4; nt++) {
                int cb = wc * 32 + nt * 8 + ly;
                unsigned b0 = Ws[cur][cb][K0 + lx];
                unsigned b1 = Ws[cur][cb][K0 + lx + 4];
                mma8(acc[0][nt], a[0][0], a[0][1], a[0][2], a[0][3], b0, b1);
                mma8(acc[1][nt], a[1][0], a[1][1], a[1][2], a[1][3], b0, b1);
            }
        }
        if (ki < 11) {
            int nxt = (ki + 1) & 1;
#pragma unroll
            for (int l = 0; l < 4; l++) {
                int idx = t + l * 128;
                int r = idx >> 3, kq = (idx & 7) << 2;
                *(uint4*)&Xs[nxt][r][kq] = make_uint4(f2tf(rx[l].x), f2tf(rx[l].y), f2tf(rx[l].z), f2tf(rx[l].w));
                *(uint4*)&Ws[nxt][r][kq] = make_uint4(f2tf(rw[l].x), f2tf(rw[l].y), f2tf(rw[l].z), f2tf(rw[l].w));
            }
        }
        __syncthreads();
    }

#pragma unroll
    for (int mi = 0; mi < 2; mi++) {
        int row = row0 + wr * 32 + mi * 16 + ly;
#pragma unroll
        for (int nt = 0; nt < 4; nt++) {
            int col = col0 + wc * 32 + nt * 8 + lx * 2;
            float b0 = bias[col], b1 = bias[col + 1];
            float2 v0; v0.x = acc[mi][nt].x + b0; v0.y = acc[mi][nt].y + b1;
            *(float2*)&OUTp[(size_t)row * DIM_ + col] = v0;
            float2 v1; v1.x = acc[mi][nt].z + b0; v1.y = acc[mi][nt].w + b1;
            *(float2*)&OUTp[(size_t)(row + 8) * DIM_ + col] = v1;
        }
    }
}

// ---------------------------------------------------------------------------
// Kernel 3: fused gated attention, dual PV, smem-slimmed for 3 blocks/SM:
//   - Q fragments live in registers (staged once through the P2 buffer)
//   - P2 (pos tile) single-buffered; cp.async group order per iter:
//     ..., P2[it], KV[it+1], P2[it+1], ...  with wait_group 1 pairings.
// ---------------------------------------------------------------------------
#define QSTR 36
#define VSTR 40
#define PSTR 68
struct ASmem {
    unsigned P1[64][PSTR];       // exp scores
    unsigned P2[64][PSTR];       // pos tile (single buffer; Q staging at start)
    unsigned Ks[2][64][QSTR];
    unsigned Vs[2][64][VSTR];
};   // 73728 B -> 3 blocks/SM

__global__ __launch_bounds__(128) void attn_kernel(const float* __restrict__ gating) {
    extern __shared__ char sraw[];
    ASmem& S = *reinterpret_cast<ASmem*>(sraw);

    int t = threadIdx.x, w = t >> 5, lane = t & 31;
    int ly = lane >> 2, lx = lane & 3;
    int bh = blockIdx.y;
    int b = bh / H_, h = bh - b * H_;
    int q0 = blockIdx.x * 64;
    int R0 = w * 16;

    const float* Qg   = g_q + (size_t)bh * N_ * HD_;
    const float* Kg   = g_k + (size_t)bh * N_ * HD_;
    const float* Vg   = g_v + (size_t)bh * N_ * HD_;
    const float* POSg = g_pos + (size_t)h * N_ * N_;

    float gate = 1.f / (1.f + __expf(-gating[h]));

    // ---- prologue: group G0 = Q (staged into P2 area, stride QSTR) + KV[0]
    unsigned (*Qa)[QSTR] = reinterpret_cast<unsigned(*)[QSTR]>(&S.P2[0][0]);
#pragma unroll
    for (int l = 0; l < 4; l++) {
        int idx = t + l * 128;
        int r = idx >> 3, dq = (idx & 7) << 2;
        cpa16(&Qa[r][dq], &Qg[(size_t)(q0 + r) * HD_ + dq], q0 + r < N_);
        bool mv = r < N_;   // m0 = 0
        cpa16(&S.Ks[0][r][dq], &Kg[(size_t)r * HD_ + dq], mv);
        cpa16(&S.Vs[0][r][dq], &Vg[(size_t)r * HD_ + dq], mv);
    }
    cpa_commit();
    asm volatile("cp.async.wait_group 0;\n" ::: "memory");
    __syncthreads();

    // Q fragments -> registers (held for the whole kernel)
    unsigned qf[4][4];
#pragma unroll
    for (int kk = 0; kk < 4; kk++) {
        int K0 = kk * 8;
        qf[kk][0] = Qa[R0 + ly][K0 + lx];
        qf[kk][1] = Qa[R0 + ly + 8][K0 + lx];
        qf[kk][2] = Qa[R0 + ly][K0 + lx + 4];
        qf[kk][3] = Qa[R0 + ly + 8][K0 + lx + 4];
    }
    __syncthreads();   // everyone done reading Q staging before P2 overwrites it

    // group G1 = P2[0]
#pragma unroll
    for (int l = 0; l < 8; l++) {
        int idx = t + l * 128;
        int r = idx >> 4, cq = (idx & 15) << 2;
        cpa16(&S.P2[r][cq], &POSg[(size_t)(q0 + r) * N_ + cq], (q0 + r < N_) && (cq < N_));
    }
    cpa_commit();

    float4 opat[4], opos[4];
#pragma unroll
    for (int i = 0; i < 4; i++) { opat[i] = make_float4(0.f,0.f,0.f,0.f); opos[i] = opat[i]; }
    float rs0 = 0.f, rs1 = 0.f;

    for (int it = 0; it < 13; it++) {
        int cur = it & 1;
        int m1 = (it + 1) * 64;
        // entering iter: outstanding = { P2[it] }
        if (it < 12) {
            int nxt = (it + 1) & 1;
#pragma unroll
            for (int l = 0; l < 4; l++) {
                int idx = t + l * 128;
                int r = idx >> 3, dq = (idx & 7) << 2;
                bool mv = m1 + r < N_;
                cpa16(&S.Ks[nxt][r][dq], &Kg[(size_t)(m1 + r) * HD_ + dq], mv);
                cpa16(&S.Vs[nxt][r][dq], &Vg[(size_t)(m1 + r) * HD_ + dq], mv);
            }
            cpa_commit();   // outstanding = { P2[it], KV[it+1] }
        }

        // S = Q K^T  (16 x 64 per warp); Ks[cur] ready from prev-iter wait
        float4 sacc[8];
#pragma unroll
        for (int i = 0; i < 8; i++) sacc[i] = make_float4(0.f,0.f,0.f,0.f);
#pragma unroll
        for (int kk = 0; kk < 4; kk++) {
            int K0 = kk * 8;
#pragma unroll
            for (int nt = 0; nt < 8; nt++) {
                unsigned b0 = S.Ks[cur][nt * 8 + ly][K0 + lx];
                unsigned b1 = S.Ks[cur][nt * 8 + ly][K0 + lx + 4];
                mma8(sacc[nt], qf[kk][0], qf[kk][1], qf[kk][2], qf[kk][3], b0, b1);
            }
        }

        // exp + rowsum + stage P1 (warp-private rows)
        int m0 = it * 64;
#pragma unroll
        for (int nt = 0; nt < 8; nt++) {
            int mc = m0 + nt * 8 + lx * 2;
            bool mv = (mc < N_);
            float ex = mv ? __expf(sacc[nt].x) : 0.f;
            float ey = mv ? __expf(sacc[nt].y) : 0.f;
            float ez = mv ? __expf(sacc[nt].z) : 0.f;
            float ew = mv ? __expf(sacc[nt].w) : 0.f;
            rs0 += ex + ey;
            rs1 += ez + ew;
            uint2 u01; u01.x = f2tf(ex); u01.y = f2tf(ey);
            uint2 u23; u23.x = f2tf(ez); u23.y = f2tf(ew);
            *(uint2*)&S.P1[R0 + ly][nt * 8 + lx * 2] = u01;
            *(uint2*)&S.P1[R0 + ly + 8][nt * 8 + lx * 2] = u23;
        }
        __syncwarp();

        // retire P2[it] (oldest outstanding group)
        if (it < 12) asm volatile("cp.async.wait_group 1;\n" ::: "memory");
        else         asm volatile("cp.async.wait_group 0;\n" ::: "memory");
        __syncthreads();

        // PV: dual accumulate (16 x 32 per warp) using P1, P2, Vs[cur]
#pragma unroll
        for (int kk = 0; kk < 8; kk++) {
            int K0 = kk * 8;
            unsigned p0 = S.P1[R0 + ly][K0 + lx];
            unsigned p1 = S.P1[R0 + ly + 8][K0 + lx];
            unsigned p2 = S.P1[R0 + ly][K0 + lx + 4];
            unsigned p3 = S.P1[R0 + ly + 8][K0 + lx + 4];
            unsigned c0 = S.P2[R0 + ly][K0 + lx];
            unsigned c1 = S.P2[R0 + ly + 8][K0 + lx];
            unsigned c2 = S.P2[R0 + ly][K0 + lx + 4];
            unsigned c3 = S.P2[R0 + ly + 8][K0 + lx + 4];
#pragma unroll
            for (int nt = 0; nt < 4; nt++) {
                unsigned b0 = S.Vs[cur][K0 + lx][nt * 8 + ly];
                unsigned b1 = S.Vs[cur][K0 + lx + 4][nt * 8 + ly];
                mma8(opat[nt], p0, p1, p2, p3, b0, b1);
                mma8(opos[nt], c0, c1, c2, c3, b0, b1);
            }
        }
        __syncthreads();   // all reads of P2 / Ks[cur] / Vs[cur] done

        if (it < 12) {
            // group P2[it+1] into the (now free) single P2 buffer
#pragma unroll
            for (int l = 0; l < 8; l++) {
                int idx = t + l * 128;
                int r = idx >> 4, cq = (idx & 15) << 2;
                cpa16(&S.P2[r][cq], &POSg[(size_t)(q0 + r) * N_ + m1 + cq],
                      (q0 + r < N_) && (m1 + cq < N_));
            }
            cpa_commit();   // outstanding = { KV[it+1], P2[it+1] }
            // retire KV[it+1] so next iter's S-phase can read it
            asm volatile("cp.async.wait_group 1;\n" ::: "memory");
            __syncthreads();
            // outstanding = { P2[it+1] }  -> loop invariant holds
        }
    }

    // rowsum reduce over the quad (lanes sharing a row)
    rs0 += __shfl_xor_sync(0xffffffffu, rs0, 1);
    rs0 += __shfl_xor_sync(0xffffffffu, rs0, 2);
    rs1 += __shfl_xor_sync(0xffffffffu, rs1, 1);
    rs1 += __shfl_xor_sync(0xffffffffu, rs1, 2);
    float inv0 = (1.f - gate) / rs0;
    float inv1 = (1.f - gate) / rs1;

    // epilogue: out = (1-g)/rowsum * O_patch + g * O_pos (attn sums to 1)
    int n0r = q0 + R0 + ly;
    int n1r = n0r + 8;
#pragma unroll
    for (int nt = 0; nt < 4; nt++) {
        int d = nt * 8 + lx * 2;
        if (n0r < N_) {
            float2 o;
            o.x = opat[nt].x * inv0 + gate * opos[nt].x;
            o.y = opat[nt].y * inv0 + gate * opos[nt].y;
            *(float2*)&g_att[((size_t)b * N_ + n0r) * DIM_ + h * HD_ + d] = o;
        }
        if (n1r < N_) {
            float2 o;
            o.x = opat[nt].z * inv1 + gate * opos[nt].z;
            o.y = opat[nt].w * inv1 + gate * opos[nt].w;
            *(float2*)&g_att[((size_t)b * N_ + n1r) * DIM_ + h * HD_ + d] = o;
        }
    }
}

// ---------------------------------------------------------------------------
extern "C" void kernel_launch(void* const* d_in, const int* in_sizes, int n_in,
                              void* d_out, int out_size) {
    const float* x      = (const float*)d_in[0];
    const float* Wq     = (const float*)d_in[1];
    const float* Wk     = (const float*)d_in[2];
    const float* Wv     = (const float*)d_in[3];
    const float* W_pos  = (const float*)d_in[4];
    const float* b_pos  = (const float*)d_in[5];
    const float* W_out  = (const float*)d_in[6];
    const float* b_out  = (const float*)d_in[7];
    const float* gating = (const float*)d_in[8];
    float* out = (float*)d_out;

    cudaFuncSetAttribute(attn_kernel, cudaFuncAttributeMaxDynamicSharedMemorySize,
                         (int)sizeof(ASmem));

    pos_kernel<<<H_ * N_, 256>>>(W_pos, b_pos);

    gemm_qkv<<<dim3(3 * DIM_ / 64, ROWS_ / 64), 128>>>(x, Wq, Wk, Wv);   // (18, 98)

    attn_kernel<<<dim3(13, B_ * H_), 128, sizeof(ASmem)>>>(gating);

    gemm_out<<<dim3(DIM_ / 64, ROWS_ / 64), 128>>>(W_out, b_out, out);   // (6, 98)
}